// round 9
// baseline (speedup 1.0000x reference)
#include <cuda_runtime.h>
#include <cuda_bf16.h>
#include <cstdint>
#include <math.h>

// ---------------- problem constants ----------------
#define Nn   50000
#define Ee   800000
#define FEAT 64
#define HID  128
#define EPSV 1e-5f
#define STATS_B 240
#define GB2 ((Nn + 63) / 64)      // 782 GEMM blocks (M-tile 64)

// ---------------- static device scratch (no allocs allowed) ----------------
__device__ float g_H   [Nn * HID];
__device__ float g_PREV[Nn * HID];
__device__ float g_Y0  [Nn * HID];
__device__ float g_T   [Nn * HID];
__device__ float g_Y   [Nn * HID];

__device__ int   g_deg   [Nn];
__device__ int   g_rowcnt[Nn];
__device__ int   g_rowptr[Nn + 1];
__device__ int   g_cursor[Nn];
__device__ float g_dinv  [Nn];
__device__ int   g_ccol  [Ee];
__device__ float g_cw    [Ee];

__device__ float g_part [STATS_B * 256];
__device__ float g_alpha[HID];
__device__ float g_beta [HID];
__device__ int   g_is64;

// pre-converted weights: 9 slots x {hi,lo} x 8192 words, k-pair packed [k2][n]
__device__ unsigned g_Wpre[9 * 2 * 8192];

// ---------------- helpers ----------------
__device__ __forceinline__ void split2(float x, float y, unsigned& hi, unsigned& lo) {
    __nv_bfloat162 h = __floats2bfloat162_rn(x, y);   // .x = k, .y = k+1
    float rx = x - __bfloat162float(h.x);
    float ry = y - __bfloat162float(h.y);
    __nv_bfloat162 l = __floats2bfloat162_rn(rx, ry);
    hi = *(unsigned*)&h;
    lo = *(unsigned*)&l;
}

#define MMA_BF16(C, A, B0, B1)                                                \
    asm volatile(                                                             \
        "mma.sync.aligned.m16n8k16.row.col.f32.bf16.bf16.f32 "                \
        "{%0,%1,%2,%3}, {%4,%5,%6,%7}, {%8,%9}, {%0,%1,%2,%3};"               \
        : "+f"((C)[0]), "+f"((C)[1]), "+f"((C)[2]), "+f"((C)[3])              \
        : "r"((A)[0]), "r"((A)[1]), "r"((A)[2]), "r"((A)[3]),                 \
          "r"(B0), "r"(B1))

// ---------------- weight pre-conversion: W[K,128] -> packed bf16 hi/lo -----
// layout: word (k2 * 128 + n) holds bf16x2 of (W[2*k2][n], W[2*k2+1][n])
__global__ void k_prepw(const float* __restrict__ W_in, const float* __restrict__ Wf,
                        const float* __restrict__ Wa, const float* __restrict__ W_o1,
                        const float* __restrict__ W_o2) {
    int s = blockIdx.x;
    const float* W; int K;
    if (s == 0)      { W = W_in;                 K = 64;  }
    else if (s < 4)  { W = Wf + (s - 1) * 16384; K = 128; }
    else if (s < 7)  { W = Wa + (s - 4) * 16384; K = 128; }
    else if (s == 7) { W = W_o1;                 K = 128; }
    else             { W = W_o2;                 K = 128; }
    int total = 128 * (K / 2);
    for (int idx = threadIdx.x; idx < total; idx += 256) {
        int n = idx & 127, k = (idx >> 7) * 2;
        float v0 = W[k * 128 + n];
        float v1 = W[(k + 1) * 128 + n];
        unsigned hi, lo; split2(v0, v1, hi, lo);
        g_Wpre[(s * 2 + 0) * 8192 + idx] = hi;
        g_Wpre[(s * 2 + 1) * 8192 + idx] = lo;
    }
}

// ---------------- split-bf16 tensor-core GEMM, M-tile 64 -------------------
// C[M,128] = A[M,K] @ W[K,128]; 3-term split (hi*hi + hi*lo + lo*hi).
// 8 warps, warp tile 16x64; A fragments direct from GMEM (register prefetch);
// B staged once to SMEM by pure uint4 copy of pre-split weights.
// EPI: 0 = +bias, 1 = sigmoid, 2 = *Mul, 3 = *Mul^2
template <int K, int EPI>
__global__ void __launch_bounds__(256, 3)
k_gemm(const float* __restrict__ A, const unsigned* __restrict__ BH,
       const unsigned* __restrict__ BL, const float* __restrict__ bias,
       const float* __restrict__ Mm, float* __restrict__ C) {
    constexpr int KP = K / 2;                 // k-pair rows of B
    constexpr int NT = K / 16;                // k tiles
    extern __shared__ unsigned smem_u[];
    unsigned (*Bs_hi)[136] = reinterpret_cast<unsigned(*)[136]>(smem_u);
    unsigned (*Bs_lo)[136] = reinterpret_cast<unsigned(*)[136]>(smem_u + KP * 136);

    const int tid    = threadIdx.x;
    const int lane   = tid & 31;
    const int warp   = tid >> 5;
    const int bm     = blockIdx.x * 64;
    const int warp_m = (warp >> 1) * 16;      // 0,16,32,48
    const int warp_n = (warp & 1) * 64;       // 0,64
    const int grp    = lane >> 2;             // 0..7
    const int tig    = lane & 3;              // 0..3

    // ---- stage B: pure uint4 copy of pre-split, pre-packed weights -------
    for (int idx = tid; idx < KP * 32; idx += 256) {
        int r = idx >> 5, c = (idx & 31) << 2;
        *(uint4*)&Bs_hi[r][c] = *(const uint4*)(BH + r * 128 + c);
        *(uint4*)&Bs_lo[r][c] = *(const uint4*)(BL + r * 128 + c);
    }

    // A fragment rows: grp and grp+8 within the warp tile
    const float* arow[2];
    bool avld[2];
#pragma unroll
    for (int r = 0; r < 2; r++) {
        int row = bm + warp_m + grp + 8 * r;
        avld[r] = row < Nn;
        arow[r] = A + (size_t)(avld[r] ? row : 0) * K + 2 * tig;
    }

    float acc[8][4];
#pragma unroll
    for (int j = 0; j < 8; j++)
#pragma unroll
        for (int i = 0; i < 4; i++) acc[j][i] = 0.f;

    // prefetch ktile 0: 2 rows x 2 k-pair segments (+0 / +8 floats)
    float2 pv[2][2];
#pragma unroll
    for (int r = 0; r < 2; r++)
#pragma unroll
        for (int p = 0; p < 2; p++)
            pv[r][p] = avld[r] ? *(const float2*)(arow[r] + 8 * p)
                               : make_float2(0.f, 0.f);

    __syncthreads();   // B ready; no further barriers until epilogue

#pragma unroll
    for (int kt = 0; kt < NT; kt++) {
        // split current prefetch into fragments (regs only)
        unsigned ahi[4], alo[4];
#pragma unroll
        for (int h = 0; h < 2; h++)
#pragma unroll
            for (int p = 0; p < 2; p++)
                split2(pv[h][p].x, pv[h][p].y, ahi[h + 2 * p], alo[h + 2 * p]);
        // prefetch next ktile (LDGs in flight during MMA phase)
        if (kt + 1 < NT) {
#pragma unroll
            for (int r = 0; r < 2; r++)
#pragma unroll
                for (int p = 0; p < 2; p++)
                    pv[r][p] = avld[r]
                        ? *(const float2*)(arow[r] + 16 * (kt + 1) + 8 * p)
                        : make_float2(0.f, 0.f);
        }

        const int koff = kt * 8;
#pragma unroll
        for (int j = 0; j < 8; j++) {
            int n = warp_n + 8 * j + grp;
            unsigned bh0 = Bs_hi[koff + tig][n];
            unsigned bh1 = Bs_hi[koff + tig + 4][n];
            unsigned bl0 = Bs_lo[koff + tig][n];
            unsigned bl1 = Bs_lo[koff + tig + 4][n];
            MMA_BF16(acc[j], ahi, bh0, bh1);
            MMA_BF16(acc[j], ahi, bl0, bl1);
            MMA_BF16(acc[j], alo, bh0, bh1);
        }
    }

    // ---- epilogue --------------------------------------------------------
#pragma unroll
    for (int j = 0; j < 8; j++) {
        int col = warp_n + 8 * j + 2 * tig;
#pragma unroll
        for (int h = 0; h < 2; h++) {
            int row = bm + warp_m + grp + 8 * h;
            if (row >= Nn) continue;
            float v0 = acc[j][2 * h + 0];
            float v1 = acc[j][2 * h + 1];
            if (EPI == 0) {
                v0 += bias[col]; v1 += bias[col + 1];
            } else if (EPI == 1) {
                v0 = 1.f / (1.f + __expf(-v0));
                v1 = 1.f / (1.f + __expf(-v1));
            } else if (EPI == 2) {
                float2 m = *(const float2*)(Mm + (size_t)row * 128 + col);
                v0 *= m.x; v1 *= m.y;
            } else if (EPI == 3) {
                float2 m = *(const float2*)(Mm + (size_t)row * 128 + col);
                v0 *= m.x * m.x; v1 *= m.y * m.y;
            }
            float2 o; o.x = v0; o.y = v1;
            *(float2*)(C + (size_t)row * 128 + col) = o;
        }
    }
}

// ---------------- graph preprocessing ----------------
__global__ void k_zero_counts() {
    int i = blockIdx.x * blockDim.x + threadIdx.x;
    if (i < Nn) { g_deg[i] = 0; g_rowcnt[i] = 0; }
}

__global__ void k_detect(const int* __restrict__ ei) {
    if (threadIdx.x == 0 && blockIdx.x == 0) {
        int all0 = 1;
        for (int i = 0; i < 32; i++) {
            if (ei[2 * i + 1] != 0) { all0 = 0; break; }
        }
        g_is64 = all0;
    }
}

__global__ void k_hist(const void* __restrict__ eiv) {
    int e = blockIdx.x * blockDim.x + threadIdx.x;
    if (e >= Ee) return;
    int r, c;
    if (g_is64) {
        const long long* p = (const long long*)eiv;
        r = (int)p[e]; c = (int)p[Ee + e];
    } else {
        const int* p = (const int*)eiv;
        r = p[e]; c = p[Ee + e];
    }
    if (r != c) {
        atomicAdd(&g_deg[c], 1);
        atomicAdd(&g_rowcnt[r], 1);
    }
}

__global__ void k_dinv() {
    int i = blockIdx.x * blockDim.x + threadIdx.x;
    if (i < Nn) g_dinv[i] = rsqrtf((float)(g_deg[i] + 1));
}

__global__ void k_scan() {
    __shared__ int s[1024];
    const int t  = threadIdx.x;
    const int CH = (Nn + 1023) / 1024;
    int base = t * CH;
    int sum = 0;
    for (int i = 0; i < CH; i++) {
        int idx = base + i;
        if (idx < Nn) sum += g_rowcnt[idx];
    }
    s[t] = sum;
    __syncthreads();
    for (int off = 1; off < 1024; off <<= 1) {
        int v = (t >= off) ? s[t - off] : 0;
        __syncthreads();
        s[t] += v;
        __syncthreads();
    }
    int run = s[t] - sum;
    for (int i = 0; i < CH; i++) {
        int idx = base + i;
        if (idx < Nn) {
            g_rowptr[idx] = run;
            g_cursor[idx] = run;
            run += g_rowcnt[idx];
        }
    }
    if (t == 1023) g_rowptr[Nn] = s[1023];
}

__global__ void k_fill(const void* __restrict__ eiv) {
    int e = blockIdx.x * blockDim.x + threadIdx.x;
    if (e >= Ee) return;
    int r, c;
    if (g_is64) {
        const long long* p = (const long long*)eiv;
        r = (int)p[e]; c = (int)p[Ee + e];
    } else {
        const int* p = (const int*)eiv;
        r = p[e]; c = p[Ee + e];
    }
    if (r != c) {
        int pos = atomicAdd(&g_cursor[r], 1);
        g_ccol[pos] = c;
        g_cw[pos]   = g_dinv[r] * g_dinv[c];
    }
}

// ---------------- SpMM: warp per row, float4 per lane, MLP=4 ----------
__global__ void __launch_bounds__(256) k_spmm(const float* __restrict__ y,
                                              float* __restrict__ out) {
    int w    = (blockIdx.x * 256 + threadIdx.x) >> 5;
    int lane = threadIdx.x & 31;
    if (w >= Nn) return;
    int s = g_rowptr[w], e = g_rowptr[w + 1];
    const float4* yv = (const float4*)y;
    float4 acc = make_float4(0.f, 0.f, 0.f, 0.f);
    int i = s;
    for (; i + 3 < e; i += 4) {
        int   c0 = __ldg(&g_ccol[i]);
        int   c1 = __ldg(&g_ccol[i + 1]);
        int   c2 = __ldg(&g_ccol[i + 2]);
        int   c3 = __ldg(&g_ccol[i + 3]);
        float w0 = __ldg(&g_cw[i]);
        float w1 = __ldg(&g_cw[i + 1]);
        float w2 = __ldg(&g_cw[i + 2]);
        float w3 = __ldg(&g_cw[i + 3]);
        float4 v0 = __ldg(&yv[(size_t)c0 * 32 + lane]);
        float4 v1 = __ldg(&yv[(size_t)c1 * 32 + lane]);
        float4 v2 = __ldg(&yv[(size_t)c2 * 32 + lane]);
        float4 v3 = __ldg(&yv[(size_t)c3 * 32 + lane]);
        acc.x = fmaf(w0, v0.x, acc.x); acc.y = fmaf(w0, v0.y, acc.y);
        acc.z = fmaf(w0, v0.z, acc.z); acc.w = fmaf(w0, v0.w, acc.w);
        acc.x = fmaf(w1, v1.x, acc.x); acc.y = fmaf(w1, v1.y, acc.y);
        acc.z = fmaf(w1, v1.z, acc.z); acc.w = fmaf(w1, v1.w, acc.w);
        acc.x = fmaf(w2, v2.x, acc.x); acc.y = fmaf(w2, v2.y, acc.y);
        acc.z = fmaf(w2, v2.z, acc.z); acc.w = fmaf(w2, v2.w, acc.w);
        acc.x = fmaf(w3, v3.x, acc.x); acc.y = fmaf(w3, v3.y, acc.y);
        acc.z = fmaf(w3, v3.z, acc.z); acc.w = fmaf(w3, v3.w, acc.w);
    }
    for (; i < e; i++) {
        int   c0 = __ldg(&g_ccol[i]);
        float w0 = __ldg(&g_cw[i]);
        float4 v0 = __ldg(&yv[(size_t)c0 * 32 + lane]);
        acc.x = fmaf(w0, v0.x, acc.x); acc.y = fmaf(w0, v0.y, acc.y);
        acc.z = fmaf(w0, v0.z, acc.z); acc.w = fmaf(w0, v0.w, acc.w);
    }
    float sw = g_dinv[w]; sw *= sw;
    float4 vs = yv[(size_t)w * 32 + lane];
    acc.x = fmaf(sw, vs.x, acc.x); acc.y = fmaf(sw, vs.y, acc.y);
    acc.z = fmaf(sw, vs.z, acc.z); acc.w = fmaf(sw, vs.w, acc.w);
    ((float4*)out)[(size_t)w * 32 + lane] = acc;
}

// ---------------- BatchNorm stats (deterministic two-stage) ----------------
__global__ void k_stats1(const float* __restrict__ X) {
    int b = blockIdx.x;
    int c = threadIdx.x;
    const int RPB = (Nn + STATS_B - 1) / STATS_B;
    int r0 = b * RPB;
    int r1 = r0 + RPB; if (r1 > Nn) r1 = Nn;
    float s = 0.f, q = 0.f;
    for (int r = r0; r < r1; r++) {
        float v = X[(size_t)r * 128 + c];
        s += v;
        q = fmaf(v, v, q);
    }
    g_part[b * 256 + c]       = s;
    g_part[b * 256 + 128 + c] = q;
}

__global__ void k_stats2(const float* __restrict__ g, const float* __restrict__ bt) {
    int c = threadIdx.x;
    float s = 0.f, q = 0.f;
    for (int b = 0; b < STATS_B; b++) {
        s += g_part[b * 256 + c];
        q += g_part[b * 256 + 128 + c];
    }
    float mean = s / (float)Nn;
    float var  = q / (float)Nn - mean * mean;
    float a = g[c] * rsqrtf(var + EPSV);
    g_alpha[c] = a;
    g_beta[c]  = bt[c] - mean * a;
}

// ---------------- BN apply (+ReLU, optional residual) ---------------------
template <int ADD>
__global__ void k_bn(const float* __restrict__ src, const float* __restrict__ prevIn,
                     float* __restrict__ dst) {
    int i = blockIdx.x * blockDim.x + threadIdx.x;
    if (i >= Nn * 32) return;
    int c = (i & 31) * 4;
    float4 v = ((const float4*)src)[i];
    v.x = fmaxf(fmaf(g_alpha[c + 0], v.x, g_beta[c + 0]), 0.f);
    v.y = fmaxf(fmaf(g_alpha[c + 1], v.y, g_beta[c + 1]), 0.f);
    v.z = fmaxf(fmaf(g_alpha[c + 2], v.z, g_beta[c + 2]), 0.f);
    v.w = fmaxf(fmaf(g_alpha[c + 3], v.w, g_beta[c + 3]), 0.f);
    if (ADD) {
        float4 p = ((const float4*)prevIn)[i];
        v.x += p.x; v.y += p.y; v.z += p.z; v.w += p.w;
    }
    ((float4*)dst)[i] = v;
}

// ---------------- launch ----------------
static int smb(int K) { return 2 * (K / 2) * 136 * 4; }

extern "C" void kernel_launch(void* const* d_in, const int* in_sizes, int n_in,
                              void* d_out, int out_size) {
    const float* x     = (const float*)d_in[0];
    const void*  ei    = d_in[1];
    const float* W_in  = (const float*)d_in[2];
    const float* b_in  = (const float*)d_in[3];
    const float* gin   = (const float*)d_in[4];
    const float* btin  = (const float*)d_in[5];
    const float* Wf    = (const float*)d_in[6];
    const float* Wa    = (const float*)d_in[7];
    const float* gnorm = (const float*)d_in[8];
    const float* btnorm= (const float*)d_in[9];
    const float* W_o1  = (const float*)d_in[10];
    const float* b_o1  = (const float*)d_in[11];
    const float* g_o   = (const float*)d_in[12];
    const float* bt_o  = (const float*)d_in[13];
    const float* W_o2  = (const float*)d_in[14];
    const float* b_o2  = (const float*)d_in[15];
    float* out = (float*)d_out;

    float *H, *PREV, *Y0, *T, *Y;
    unsigned* wpre;
    cudaGetSymbolAddress((void**)&H,    g_H);
    cudaGetSymbolAddress((void**)&PREV, g_PREV);
    cudaGetSymbolAddress((void**)&Y0,   g_Y0);
    cudaGetSymbolAddress((void**)&T,    g_T);
    cudaGetSymbolAddress((void**)&Y,    g_Y);
    cudaGetSymbolAddress((void**)&wpre, g_Wpre);
    auto wh = [&](int s) { return wpre + (size_t)(s * 2 + 0) * 8192; };
    auto wl = [&](int s) { return wpre + (size_t)(s * 2 + 1) * 8192; };

    cudaFuncSetAttribute(k_gemm<64, 0>,  cudaFuncAttributeMaxDynamicSharedMemorySize, smb(64));
    cudaFuncSetAttribute(k_gemm<128, 0>, cudaFuncAttributeMaxDynamicSharedMemorySize, smb(128));
    cudaFuncSetAttribute(k_gemm<128, 1>, cudaFuncAttributeMaxDynamicSharedMemorySize, smb(128));
    cudaFuncSetAttribute(k_gemm<128, 2>, cudaFuncAttributeMaxDynamicSharedMemorySize, smb(128));
    cudaFuncSetAttribute(k_gemm<128, 3>, cudaFuncAttributeMaxDynamicSharedMemorySize, smb(128));

    const int NB  = (Nn + 255) / 256;
    const int EB  = (Ee + 255) / 256;
    const int EWB = (Nn * 32 + 255) / 256;

    k_zero_counts<<<NB, 256>>>();                                        // 0
    k_prepw<<<9, 256>>>(W_in, Wf, Wa, W_o1, W_o2);                       // 1
    k_detect<<<1, 32>>>((const int*)ei);                                 // 2
    k_gemm<64, 0><<<GB2, 256, smb(64)>>>(x, wh(0), wl(0), b_in, nullptr, T); // 3 <- profiled
    k_hist<<<EB, 256>>>(ei);                                             // 4
    k_dinv<<<NB, 256>>>();                                               // 5
    k_scan<<<1, 1024>>>();                                               // 6
    k_fill<<<EB, 256>>>(ei);                                             // 7
    k_stats1<<<STATS_B, 128>>>(T);                                       // 8
    k_stats2<<<1, 128>>>(gin, btin);                                     // 9
    k_bn<0><<<EWB, 256>>>(T, nullptr, PREV);                             // 10

    for (int l = 0; l < 3; l++) {
        k_gemm<128, 1><<<GB2, 256, smb(128)>>>(PREV, wh(1 + l), wl(1 + l), nullptr, nullptr, Y0);
        k_spmm<<<EWB, 256>>>(Y0, T);
        k_gemm<128, 3><<<GB2, 256, smb(128)>>>(T, wh(4 + l), wl(4 + l), nullptr, Y0, Y);
        k_spmm<<<EWB, 256>>>(Y, T);
        k_gemm<128, 2><<<GB2, 256, smb(128)>>>(T, wh(4 + l), wl(4 + l), nullptr, Y0, H);
        if (l < 2) {
            k_stats1<<<STATS_B, 128>>>(H);
            k_stats2<<<1, 128>>>(gnorm + l * 128, btnorm + l * 128);
            k_bn<1><<<EWB, 256>>>(H, PREV, PREV);
        }
    }

    k_gemm<128, 0><<<GB2, 256, smb(128)>>>(H, wh(7), wl(7), b_o1, nullptr, T);
    k_stats1<<<STATS_B, 128>>>(T);
    k_stats2<<<1, 128>>>(g_o, bt_o);
    k_bn<0><<<EWB, 256>>>(T, nullptr, Y0);
    k_gemm<128, 0><<<GB2, 256, smb(128)>>>(Y0, wh(8), wl(8), b_o2, nullptr, out);
}

// round 10
// speedup vs baseline: 1.0808x; 1.0808x over previous
#include <cuda_runtime.h>
#include <cuda_bf16.h>
#include <cuda_fp16.h>
#include <cstdint>
#include <math.h>

// ---------------- problem constants ----------------
#define Nn   50000
#define Ee   800000
#define FEAT 64
#define HID  128
#define EPSV 1e-5f
#define STATS_B 240
#define GB1 ((Nn + 127) / 128)    // 391 GEMM blocks (M-tile 128)

// ---------------- static device scratch (no allocs allowed) ----------------
__device__ float  g_H   [Nn * HID];
__device__ float  g_PREV[Nn * HID];
__device__ float  g_Y0  [Nn * HID];
__device__ float  g_T   [Nn * HID];
__device__ float  g_Y   [Nn * HID];
__device__ __half g_YH  [Nn * HID];   // fp16 gather matrix for SpMM

__device__ int   g_deg   [Nn];
__device__ int   g_rowcnt[Nn];
__device__ int   g_rowptr[Nn + 1];
__device__ int   g_cursor[Nn];
__device__ float g_dinv  [Nn];
__device__ int   g_ccol  [Ee];
__device__ float g_cw    [Ee];

__device__ float g_part [STATS_B * 256];
__device__ float g_alpha[HID];
__device__ float g_beta [HID];
__device__ int   g_is64;

// pre-converted weights: 9 slots x {hi,lo} x 8192 words, k-pair packed [k2][n]
__device__ unsigned g_Wpre[9 * 2 * 8192];

// ---------------- helpers ----------------
__device__ __forceinline__ void split2(float x, float y, unsigned& hi, unsigned& lo) {
    __nv_bfloat162 h = __floats2bfloat162_rn(x, y);   // .x = k, .y = k+1
    float rx = x - __bfloat162float(h.x);
    float ry = y - __bfloat162float(h.y);
    __nv_bfloat162 l = __floats2bfloat162_rn(rx, ry);
    hi = *(unsigned*)&h;
    lo = *(unsigned*)&l;
}

#define MMA_BF16(C, A, B0, B1)                                                \
    asm volatile(                                                             \
        "mma.sync.aligned.m16n8k16.row.col.f32.bf16.bf16.f32 "                \
        "{%0,%1,%2,%3}, {%4,%5,%6,%7}, {%8,%9}, {%0,%1,%2,%3};"               \
        : "+f"((C)[0]), "+f"((C)[1]), "+f"((C)[2]), "+f"((C)[3])              \
        : "r"((A)[0]), "r"((A)[1]), "r"((A)[2]), "r"((A)[3]),                 \
          "r"(B0), "r"(B1))

// ---------------- weight pre-conversion: W[K,128] -> packed bf16 hi/lo -----
// layout: word (k2 * 128 + n) holds bf16x2 of (W[2*k2][n], W[2*k2+1][n])
__global__ void k_prepw(const float* __restrict__ W_in, const float* __restrict__ Wf,
                        const float* __restrict__ Wa, const float* __restrict__ W_o1,
                        const float* __restrict__ W_o2) {
    int s = blockIdx.x;
    const float* W; int K;
    if (s == 0)      { W = W_in;                 K = 64;  }
    else if (s < 4)  { W = Wf + (s - 1) * 16384; K = 128; }
    else if (s < 7)  { W = Wa + (s - 4) * 16384; K = 128; }
    else if (s == 7) { W = W_o1;                 K = 128; }
    else             { W = W_o2;                 K = 128; }
    int total = 128 * (K / 2);
    for (int idx = threadIdx.x; idx < total; idx += 256) {
        int n = idx & 127, k = (idx >> 7) * 2;
        float v0 = W[k * 128 + n];
        float v1 = W[(k + 1) * 128 + n];
        unsigned hi, lo; split2(v0, v1, hi, lo);
        g_Wpre[(s * 2 + 0) * 8192 + idx] = hi;
        g_Wpre[(s * 2 + 1) * 8192 + idx] = lo;
    }
}

// ---------------- split-bf16 tensor-core GEMM, M-tile 128 ------------------
// C[M,128] = A[M,K] @ W[K,128]; 3-term split (hi*hi + hi*lo + lo*hi).
// 8 warps, warp tile 32x64; A fragments direct from GMEM (register prefetch);
// B staged once to SMEM by pure uint4 copy of pre-split weights.
// EPI: 0 = +bias, 1 = sigmoid, 2 = *Mul, 3 = *Mul^2
// WH: also write fp16 copy to g_YH; WF: write fp32 C
template <int K, int EPI, int WH, int WF>
__global__ void __launch_bounds__(256, 2)
k_gemm(const float* __restrict__ A, const unsigned* __restrict__ BH,
       const unsigned* __restrict__ BL, const float* __restrict__ bias,
       const float* __restrict__ Mm, float* __restrict__ C) {
    constexpr int KP = K / 2;                 // k-pair rows of B
    constexpr int NT = K / 16;                // k tiles
    extern __shared__ unsigned smem_u[];
    unsigned (*Bs_hi)[136] = reinterpret_cast<unsigned(*)[136]>(smem_u);
    unsigned (*Bs_lo)[136] = reinterpret_cast<unsigned(*)[136]>(smem_u + KP * 136);

    const int tid    = threadIdx.x;
    const int lane   = tid & 31;
    const int warp   = tid >> 5;
    const int bm     = blockIdx.x * 128;
    const int warp_m = (warp >> 1) * 32;
    const int warp_n = (warp & 1) * 64;
    const int grp    = lane >> 2;
    const int tig    = lane & 3;

    // ---- stage B: pure uint4 copy of pre-split, pre-packed weights -------
    for (int idx = tid; idx < KP * 32; idx += 256) {
        int r = idx >> 5, c = (idx & 31) << 2;
        *(uint4*)&Bs_hi[r][c] = *(const uint4*)(BH + r * 128 + c);
        *(uint4*)&Bs_lo[r][c] = *(const uint4*)(BL + r * 128 + c);
    }

    // A fragment row pointers: rows r = 2t + h -> warp_m + 16t + 8h + grp
    const float* arow[4];
    bool avld[4];
#pragma unroll
    for (int r = 0; r < 4; r++) {
        int row = bm + warp_m + 16 * (r >> 1) + 8 * (r & 1) + grp;
        avld[r] = row < Nn;
        arow[r] = A + (size_t)(avld[r] ? row : 0) * K + 2 * tig;
    }

    float acc[2][8][4];
#pragma unroll
    for (int t = 0; t < 2; t++)
#pragma unroll
        for (int j = 0; j < 8; j++)
#pragma unroll
            for (int i = 0; i < 4; i++) acc[t][j][i] = 0.f;

    // prefetch ktile 0: 4 rows x 2 kpair-segments (p: +0 / +8 floats)
    float2 pv[4][2];
#pragma unroll
    for (int r = 0; r < 4; r++)
#pragma unroll
        for (int p = 0; p < 2; p++)
            pv[r][p] = avld[r] ? *(const float2*)(arow[r] + 8 * p)
                               : make_float2(0.f, 0.f);

    __syncthreads();   // B ready; no further barriers

#pragma unroll
    for (int kt = 0; kt < NT; kt++) {
        unsigned ahi[2][4], alo[2][4];
#pragma unroll
        for (int t = 0; t < 2; t++)
#pragma unroll
            for (int h = 0; h < 2; h++)
#pragma unroll
                for (int p = 0; p < 2; p++)
                    split2(pv[2 * t + h][p].x, pv[2 * t + h][p].y,
                           ahi[t][h + 2 * p], alo[t][h + 2 * p]);
        if (kt + 1 < NT) {
#pragma unroll
            for (int r = 0; r < 4; r++)
#pragma unroll
                for (int p = 0; p < 2; p++)
                    pv[r][p] = avld[r]
                        ? *(const float2*)(arow[r] + 16 * (kt + 1) + 8 * p)
                        : make_float2(0.f, 0.f);
        }

        const int koff = kt * 8;
#pragma unroll
        for (int j = 0; j < 8; j++) {
            int n = warp_n + 8 * j + grp;
            unsigned bh0 = Bs_hi[koff + tig][n];
            unsigned bh1 = Bs_hi[koff + tig + 4][n];
            unsigned bl0 = Bs_lo[koff + tig][n];
            unsigned bl1 = Bs_lo[koff + tig + 4][n];
#pragma unroll
            for (int t = 0; t < 2; t++) {
                MMA_BF16(acc[t][j], ahi[t], bh0, bh1);
                MMA_BF16(acc[t][j], ahi[t], bl0, bl1);
                MMA_BF16(acc[t][j], alo[t], bh0, bh1);
            }
        }
    }

    // ---- epilogue --------------------------------------------------------
#pragma unroll
    for (int j = 0; j < 8; j++) {
        int col = warp_n + 8 * j + 2 * tig;
#pragma unroll
        for (int t = 0; t < 2; t++) {
#pragma unroll
            for (int h = 0; h < 2; h++) {
                int row = bm + warp_m + 16 * t + grp + h * 8;
                if (row >= Nn) continue;
                float v0 = acc[t][j][h * 2 + 0];
                float v1 = acc[t][j][h * 2 + 1];
                if (EPI == 0) {
                    v0 += bias[col]; v1 += bias[col + 1];
                } else if (EPI == 1) {
                    v0 = 1.f / (1.f + __expf(-v0));
                    v1 = 1.f / (1.f + __expf(-v1));
                } else if (EPI == 2) {
                    float2 m = *(const float2*)(Mm + (size_t)row * 128 + col);
                    v0 *= m.x; v1 *= m.y;
                } else if (EPI == 3) {
                    float2 m = *(const float2*)(Mm + (size_t)row * 128 + col);
                    v0 *= m.x * m.x; v1 *= m.y * m.y;
                }
                if (WF) {
                    float2 o; o.x = v0; o.y = v1;
                    *(float2*)(C + (size_t)row * 128 + col) = o;
                }
                if (WH) {
                    *(__half2*)(g_YH + (size_t)row * 128 + col) =
                        __floats2half2_rn(v0, v1);
                }
            }
        }
    }
}

// ---------------- graph preprocessing ----------------
__global__ void k_zero_counts() {
    int i = blockIdx.x * blockDim.x + threadIdx.x;
    if (i < Nn) { g_deg[i] = 0; g_rowcnt[i] = 0; }
}

__global__ void k_detect(const int* __restrict__ ei) {
    if (threadIdx.x == 0 && blockIdx.x == 0) {
        int all0 = 1;
        for (int i = 0; i < 32; i++) {
            if (ei[2 * i + 1] != 0) { all0 = 0; break; }
        }
        g_is64 = all0;
    }
}

__global__ void k_hist(const void* __restrict__ eiv) {
    int e = blockIdx.x * blockDim.x + threadIdx.x;
    if (e >= Ee) return;
    int r, c;
    if (g_is64) {
        const long long* p = (const long long*)eiv;
        r = (int)p[e]; c = (int)p[Ee + e];
    } else {
        const int* p = (const int*)eiv;
        r = p[e]; c = p[Ee + e];
    }
    if (r != c) {
        atomicAdd(&g_deg[c], 1);
        atomicAdd(&g_rowcnt[r], 1);
    }
}

__global__ void k_dinv() {
    int i = blockIdx.x * blockDim.x + threadIdx.x;
    if (i < Nn) g_dinv[i] = rsqrtf((float)(g_deg[i] + 1));
}

__global__ void k_scan() {
    __shared__ int s[1024];
    const int t  = threadIdx.x;
    const int CH = (Nn + 1023) / 1024;
    int base = t * CH;
    int sum = 0;
    for (int i = 0; i < CH; i++) {
        int idx = base + i;
        if (idx < Nn) sum += g_rowcnt[idx];
    }
    s[t] = sum;
    __syncthreads();
    for (int off = 1; off < 1024; off <<= 1) {
        int v = (t >= off) ? s[t - off] : 0;
        __syncthreads();
        s[t] += v;
        __syncthreads();
    }
    int run = s[t] - sum;
    for (int i = 0; i < CH; i++) {
        int idx = base + i;
        if (idx < Nn) {
            g_rowptr[idx] = run;
            g_cursor[idx] = run;
            run += g_rowcnt[idx];
        }
    }
    if (t == 1023) g_rowptr[Nn] = s[1023];
}

__global__ void k_fill(const void* __restrict__ eiv) {
    int e = blockIdx.x * blockDim.x + threadIdx.x;
    if (e >= Ee) return;
    int r, c;
    if (g_is64) {
        const long long* p = (const long long*)eiv;
        r = (int)p[e]; c = (int)p[Ee + e];
    } else {
        const int* p = (const int*)eiv;
        r = p[e]; c = p[Ee + e];
    }
    if (r != c) {
        int pos = atomicAdd(&g_cursor[r], 1);
        g_ccol[pos] = c;
        g_cw[pos]   = g_dinv[r] * g_dinv[c];
    }
}

// ---------------- SpMM: fp16 gather (g_YH), fp32 accumulate ----------------
// warp per row; lane covers cols 4*lane..4*lane+3 (8 bytes = uint2 per edge)
__global__ void __launch_bounds__(256) k_spmm(float* __restrict__ out) {
    int w    = (blockIdx.x * 256 + threadIdx.x) >> 5;
    int lane = threadIdx.x & 31;
    if (w >= Nn) return;
    int s = g_rowptr[w], e = g_rowptr[w + 1];
    const uint2* yh = (const uint2*)g_YH;   // 4 halfs per uint2; row stride 32
    float4 acc = make_float4(0.f, 0.f, 0.f, 0.f);
    int i = s;
    for (; i + 3 < e; i += 4) {
        int   c0 = __ldg(&g_ccol[i]);
        int   c1 = __ldg(&g_ccol[i + 1]);
        int   c2 = __ldg(&g_ccol[i + 2]);
        int   c3 = __ldg(&g_ccol[i + 3]);
        float w0 = __ldg(&g_cw[i]);
        float w1 = __ldg(&g_cw[i + 1]);
        float w2 = __ldg(&g_cw[i + 2]);
        float w3 = __ldg(&g_cw[i + 3]);
        uint2 r0 = __ldg(&yh[(size_t)c0 * 32 + lane]);
        uint2 r1 = __ldg(&yh[(size_t)c1 * 32 + lane]);
        uint2 r2 = __ldg(&yh[(size_t)c2 * 32 + lane]);
        uint2 r3 = __ldg(&yh[(size_t)c3 * 32 + lane]);
        float2 a0 = __half22float2(*(__half2*)&r0.x), b0 = __half22float2(*(__half2*)&r0.y);
        float2 a1 = __half22float2(*(__half2*)&r1.x), b1 = __half22float2(*(__half2*)&r1.y);
        float2 a2 = __half22float2(*(__half2*)&r2.x), b2 = __half22float2(*(__half2*)&r2.y);
        float2 a3 = __half22float2(*(__half2*)&r3.x), b3 = __half22float2(*(__half2*)&r3.y);
        acc.x = fmaf(w0, a0.x, acc.x); acc.y = fmaf(w0, a0.y, acc.y);
        acc.z = fmaf(w0, b0.x, acc.z); acc.w = fmaf(w0, b0.y, acc.w);
        acc.x = fmaf(w1, a1.x, acc.x); acc.y = fmaf(w1, a1.y, acc.y);
        acc.z = fmaf(w1, b1.x, acc.z); acc.w = fmaf(w1, b1.y, acc.w);
        acc.x = fmaf(w2, a2.x, acc.x); acc.y = fmaf(w2, a2.y, acc.y);
        acc.z = fmaf(w2, b2.x, acc.z); acc.w = fmaf(w2, b2.y, acc.w);
        acc.x = fmaf(w3, a3.x, acc.x); acc.y = fmaf(w3, a3.y, acc.y);
        acc.z = fmaf(w3, b3.x, acc.z); acc.w = fmaf(w3, b3.y, acc.w);
    }
    for (; i < e; i++) {
        int   c0 = __ldg(&g_ccol[i]);
        float w0 = __ldg(&g_cw[i]);
        uint2 r0 = __ldg(&yh[(size_t)c0 * 32 + lane]);
        float2 a0 = __half22float2(*(__half2*)&r0.x), b0 = __half22float2(*(__half2*)&r0.y);
        acc.x = fmaf(w0, a0.x, acc.x); acc.y = fmaf(w0, a0.y, acc.y);
        acc.z = fmaf(w0, b0.x, acc.z); acc.w = fmaf(w0, b0.y, acc.w);
    }
    // self loop: weight = dinv^2
    float sw = g_dinv[w]; sw *= sw;
    uint2 rs = yh[(size_t)w * 32 + lane];
    float2 as = __half22float2(*(__half2*)&rs.x), bs = __half22float2(*(__half2*)&rs.y);
    acc.x = fmaf(sw, as.x, acc.x); acc.y = fmaf(sw, as.y, acc.y);
    acc.z = fmaf(sw, bs.x, acc.z); acc.w = fmaf(sw, bs.y, acc.w);
    ((float4*)out)[(size_t)w * 32 + lane] = acc;
}

// ---------------- BatchNorm stats (deterministic two-stage) ----------------
__global__ void k_stats1(const float* __restrict__ X) {
    int b = blockIdx.x;
    int c = threadIdx.x;
    const int RPB = (Nn + STATS_B - 1) / STATS_B;
    int r0 = b * RPB;
    int r1 = r0 + RPB; if (r1 > Nn) r1 = Nn;
    float s = 0.f, q = 0.f;
    for (int r = r0; r < r1; r++) {
        float v = X[(size_t)r * 128 + c];
        s += v;
        q = fmaf(v, v, q);
    }
    g_part[b * 256 + c]       = s;
    g_part[b * 256 + 128 + c] = q;
}

__global__ void k_stats2(const float* __restrict__ g, const float* __restrict__ bt) {
    int c = threadIdx.x;
    float s = 0.f, q = 0.f;
    for (int b = 0; b < STATS_B; b++) {
        s += g_part[b * 256 + c];
        q += g_part[b * 256 + 128 + c];
    }
    float mean = s / (float)Nn;
    float var  = q / (float)Nn - mean * mean;
    float a = g[c] * rsqrtf(var + EPSV);
    g_alpha[c] = a;
    g_beta[c]  = bt[c] - mean * a;
}

// ---------------- BN apply (+ReLU, optional residual) ---------------------
template <int ADD>
__global__ void k_bn(const float* __restrict__ src, const float* __restrict__ prevIn,
                     float* __restrict__ dst) {
    int i = blockIdx.x * blockDim.x + threadIdx.x;
    if (i >= Nn * 32) return;
    int c = (i & 31) * 4;
    float4 v = ((const float4*)src)[i];
    v.x = fmaxf(fmaf(g_alpha[c + 0], v.x, g_beta[c + 0]), 0.f);
    v.y = fmaxf(fmaf(g_alpha[c + 1], v.y, g_beta[c + 1]), 0.f);
    v.z = fmaxf(fmaf(g_alpha[c + 2], v.z, g_beta[c + 2]), 0.f);
    v.w = fmaxf(fmaf(g_alpha[c + 3], v.w, g_beta[c + 3]), 0.f);
    if (ADD) {
        float4 p = ((const float4*)prevIn)[i];
        v.x += p.x; v.y += p.y; v.z += p.z; v.w += p.w;
    }
    ((float4*)dst)[i] = v;
}

// ---------------- launch ----------------
static int smb(int K) { return 2 * (K / 2) * 136 * 4; }

extern "C" void kernel_launch(void* const* d_in, const int* in_sizes, int n_in,
                              void* d_out, int out_size) {
    const float* x     = (const float*)d_in[0];
    const void*  ei    = d_in[1];
    const float* W_in  = (const float*)d_in[2];
    const float* b_in  = (const float*)d_in[3];
    const float* gin   = (const float*)d_in[4];
    const float* btin  = (const float*)d_in[5];
    const float* Wf    = (const float*)d_in[6];
    const float* Wa    = (const float*)d_in[7];
    const float* gnorm = (const float*)d_in[8];
    const float* btnorm= (const float*)d_in[9];
    const float* W_o1  = (const float*)d_in[10];
    const float* b_o1  = (const float*)d_in[11];
    const float* g_o   = (const float*)d_in[12];
    const float* bt_o  = (const float*)d_in[13];
    const float* W_o2  = (const float*)d_in[14];
    const float* b_o2  = (const float*)d_in[15];
    float* out = (float*)d_out;

    float *H, *PREV, *Y0, *T, *Y;
    unsigned* wpre;
    cudaGetSymbolAddress((void**)&H,    g_H);
    cudaGetSymbolAddress((void**)&PREV, g_PREV);
    cudaGetSymbolAddress((void**)&Y0,   g_Y0);
    cudaGetSymbolAddress((void**)&T,    g_T);
    cudaGetSymbolAddress((void**)&Y,    g_Y);
    cudaGetSymbolAddress((void**)&wpre, g_Wpre);
    auto wh = [&](int s) { return wpre + (size_t)(s * 2 + 0) * 8192; };
    auto wl = [&](int s) { return wpre + (size_t)(s * 2 + 1) * 8192; };

    cudaFuncSetAttribute(k_gemm<64, 0, 0, 1>,  cudaFuncAttributeMaxDynamicSharedMemorySize, smb(64));
    cudaFuncSetAttribute(k_gemm<128, 1, 1, 1>, cudaFuncAttributeMaxDynamicSharedMemorySize, smb(128));
    cudaFuncSetAttribute(k_gemm<128, 3, 1, 0>, cudaFuncAttributeMaxDynamicSharedMemorySize, smb(128));
    cudaFuncSetAttribute(k_gemm<128, 2, 0, 1>, cudaFuncAttributeMaxDynamicSharedMemorySize, smb(128));
    cudaFuncSetAttribute(k_gemm<128, 0, 0, 1>, cudaFuncAttributeMaxDynamicSharedMemorySize, smb(128));

    const int NB  = (Nn + 255) / 256;
    const int EB  = (Ee + 255) / 256;
    const int EWB = (Nn * 32 + 255) / 256;

    k_zero_counts<<<NB, 256>>>();                                        // 0
    k_prepw<<<9, 256>>>(W_in, Wf, Wa, W_o1, W_o2);                       // 1
    k_detect<<<1, 32>>>((const int*)ei);                                 // 2
    k_gemm<64, 0, 0, 1><<<GB1, 256, smb(64)>>>(x, wh(0), wl(0), b_in, nullptr, T); // 3 <- profiled
    k_hist<<<EB, 256>>>(ei);                                             // 4
    k_dinv<<<NB, 256>>>();                                               // 5
    k_scan<<<1, 1024>>>();                                               // 6
    k_fill<<<EB, 256>>>(ei);                                             // 7
    k_stats1<<<STATS_B, 128>>>(T);                                       // 8
    k_stats2<<<1, 128>>>(gin, btin);                                     // 9
    k_bn<0><<<EWB, 256>>>(T, nullptr, PREV);                             // 10

    for (int l = 0; l < 3; l++) {
        // y0 = sigmoid(PREV @ Wf): fp32 -> Y0, fp16 -> g_YH
        k_gemm<128, 1, 1, 1><<<GB1, 256, smb(128)>>>(PREV, wh(1 + l), wl(1 + l), nullptr, nullptr, Y0);
        k_spmm<<<EWB, 256>>>(T);     // T = A_hat @ y0 (fp16 gather)
        // y = y0^2 * (T @ Wa): fp16 only -> g_YH (fp32 output dead)
        k_gemm<128, 3, 1, 0><<<GB1, 256, smb(128)>>>(T, wh(4 + l), wl(4 + l), nullptr, Y0, Y);
        k_spmm<<<EWB, 256>>>(T);     // T = A_hat @ y
        // h = y0 * (T @ Wa)
        k_gemm<128, 2, 0, 1><<<GB1, 256, smb(128)>>>(T, wh(4 + l), wl(4 + l), nullptr, Y0, H);
        if (l < 2) {
            k_stats1<<<STATS_B, 128>>>(H);
            k_stats2<<<1, 128>>>(gnorm + l * 128, btnorm + l * 128);
            k_bn<1><<<EWB, 256>>>(H, PREV, PREV);
        }
    }

    k_gemm<128, 0, 0, 1><<<GB1, 256, smb(128)>>>(H, wh(7), wl(7), b_o1, nullptr, T);
    k_stats1<<<STATS_B, 128>>>(T);
    k_stats2<<<1, 128>>>(g_o, bt_o);
    k_bn<0><<<EWB, 256>>>(T, nullptr, Y0);
    k_gemm<128, 0, 0, 1><<<GB1, 256, smb(128)>>>(Y0, wh(8), wl(8), b_o2, nullptr, out);
}